// round 11
// baseline (speedup 1.0000x reference)
#include <cuda_runtime.h>
#include <cuda_fp16.h>
#include <mma.h>
#include <math.h>

using namespace nvcuda;

// Problem constants (fixed shapes)
#define NN 100000
#define NE 1600000
#define NG 512
#define FIN 128
#define HH 64
#define HS 192   // 3*H concat width
#define GF 576   // 3*HS graph feature width

#define SCAN_CH 1024
#define NSB ((NN + SCAN_CH - 1) / SCAN_CH)   // 98 scan blocks

// ---------------- scratch (static device globals; no runtime alloc) -------
// +64-row padding lets GEMM tiles store unguarded past NN.
__device__ __align__(16) __half g_y16[(size_t)(NN + 64) * HH];   // projected feats
__device__ __align__(16) __half g_hs16[(size_t)(NN + 64) * HS];  // concat outputs
__device__ __align__(16) __half g_w1h0[FIN * HH];     // W1 layer0 fp16
__device__ __align__(16) __half g_w1hn[2][HH * HH];   // W1 layers 1,2 fp16
__device__ __align__(16) __half g_w2h[3][HH * HH];    // W2 all layers fp16
__device__ __align__(16) int g_rowptr[NN + 4];
__device__ __align__(16) int g_cursor[NN + 4];
__device__ int g_csr[NE];
__device__ int g_bsum[NSB];
__device__ int g_boff[NSB + 1];
__device__ int g_is64;

// ---------------- index dtype handling -------------------------------------
__device__ __forceinline__ long ld_idx(const void* p, long i) {
    if (g_is64) return (long)((const long long*)p)[i];
    return (long)((const int*)p)[i];
}

// ---------------- prep: dtype probe + zero degrees + weight fp16 convert ---
__global__ void k_prep(const void* edge,
                       const float* __restrict__ w10, const float* __restrict__ w11,
                       const float* __restrict__ w12, const float* __restrict__ w20,
                       const float* __restrict__ w21, const float* __restrict__ w22) {
    int i = blockIdx.x * 256 + threadIdx.x;
    if (blockIdx.x == 0 && threadIdx.x < 32) {
        // int64 indices < 2^31 => every odd 32-bit word is zero.
        const int* p = (const int*)edge;
        int nz = (p[2 * threadIdx.x + 1] != 0) ? 1 : 0;
        unsigned m = __ballot_sync(0xffffffffu, nz);
        if (threadIdx.x == 0) g_is64 = (m == 0) ? 1 : 0;
    }
    if (i < NN) g_cursor[i] = 0;
    if (i < 8192)       g_w1h0[i]            = __float2half_rn(w10[i]);
    else if (i < 12288) g_w1hn[0][i - 8192]  = __float2half_rn(w11[i - 8192]);
    else if (i < 16384) g_w1hn[1][i - 12288] = __float2half_rn(w12[i - 12288]);
    else if (i < 20480) g_w2h[0][i - 16384]  = __float2half_rn(w20[i - 16384]);
    else if (i < 24576) g_w2h[1][i - 20480]  = __float2half_rn(w21[i - 20480]);
    else if (i < 28672) g_w2h[2][i - 24576]  = __float2half_rn(w22[i - 24576]);
}

// ---------------- CSR build ------------------------------------------------
__global__ void k_deg(const void* __restrict__ edge) {
    long e = (long)blockIdx.x * 256 + threadIdx.x;
    if (e < NE) {
        int d = (int)ld_idx(edge, (long)NE + e);
        atomicAdd(&g_cursor[d], 1);
    }
}

__global__ void __launch_bounds__(256) k_bsum() {
    __shared__ int ws[8];
    const int b = blockIdx.x, t = threadIdx.x;
    const int base = b * SCAN_CH + t * 4;
    int s = 0;
    if (base < NN) {
        int4 v = *(const int4*)&g_cursor[base];
        s = (v.x + v.y) + (v.z + v.w);
    }
#pragma unroll
    for (int o = 16; o > 0; o >>= 1) s += __shfl_down_sync(0xffffffffu, s, o);
    if ((t & 31) == 0) ws[t >> 5] = s;
    __syncthreads();
    if (t < 8) {
        int v = ws[t];
#pragma unroll
        for (int o = 4; o > 0; o >>= 1) v += __shfl_down_sync(0xffu, v, o);
        if (t == 0) g_bsum[b] = v;
    }
}

__global__ void __launch_bounds__(128) k_bscan() {
    __shared__ int s[128];
    int t = threadIdx.x;
    int v = (t < NSB) ? g_bsum[t] : 0;
    s[t] = v;
    __syncthreads();
#pragma unroll
    for (int d = 1; d < 128; d <<= 1) {
        int u = (t >= d) ? s[t - d] : 0;
        __syncthreads();
        s[t] += u;
        __syncthreads();
    }
    g_boff[t] = (t == 0) ? 0 : s[t - 1];
    if (t == NSB - 1) g_rowptr[NN] = s[t];
}

__global__ void __launch_bounds__(256) k_rowptr() {
    __shared__ int s[256];
    const int b = blockIdx.x, t = threadIdx.x;
    const int base = b * SCAN_CH + t * 4;
    int d0 = 0, d1 = 0, d2 = 0, d3 = 0;
    if (base < NN) {
        int4 v = *(const int4*)&g_cursor[base];
        d0 = v.x; d1 = v.y; d2 = v.z; d3 = v.w;
    }
    s[t] = d0 + d1 + d2 + d3;
    __syncthreads();
#pragma unroll
    for (int d = 1; d < 256; d <<= 1) {
        int u = (t >= d) ? s[t - d] : 0;
        __syncthreads();
        s[t] += u;
        __syncthreads();
    }
    int off = g_boff[b] + ((t == 0) ? 0 : s[t - 1]);
    if (base < NN) {
        int4 r;
        r.x = off;
        r.y = off + d0;
        r.z = off + d0 + d1;
        r.w = off + d0 + d1 + d2;
        *(int4*)&g_rowptr[base] = r;
        *(int4*)&g_cursor[base] = r;
    }
}

__global__ void k_fill(const void* __restrict__ edge) {
    long e = (long)blockIdx.x * 256 + threadIdx.x;
    if (e < NE) {
        int s = (int)ld_idx(edge, e);
        int d = (int)ld_idx(edge, (long)NE + e);
        int pos = atomicAdd(&g_cursor[d], 1);
        g_csr[pos] = s;
    }
}

// ---------------- helpers ---------------------------------------------------
__device__ __forceinline__ void f4_to_h4(const float4& v, __half* dst) {
    __half2 h01 = __floats2half2_rn(v.x, v.y);
    __half2 h23 = __floats2half2_rn(v.z, v.w);
    uint2 u;
    u.x = *(unsigned*)&h01;
    u.y = *(unsigned*)&h23;
    *(uint2*)dst = u;
}

__device__ __forceinline__ void acc8(const uint4& r, float2& a0, float2& a1,
                                     float2& a2, float2& a3) {
    float2 p;
    p = __half22float2(*(const __half2*)&r.x); a0.x += p.x; a0.y += p.y;
    p = __half22float2(*(const __half2*)&r.y); a1.x += p.x; a1.y += p.y;
    p = __half22float2(*(const __half2*)&r.z); a2.x += p.x; a2.y += p.y;
    p = __half22float2(*(const __half2*)&r.w); a3.x += p.x; a3.y += p.y;
}

// ---------------- GEMM1 (layer 0 only): y0 = x @ W1_0, tensor cores --------
__global__ void __launch_bounds__(256) k_gemm1(const float* __restrict__ x) {
    __shared__ __align__(16) __half sA[64][136];   // 64x128 (+8 pad)
    __shared__ __align__(16) __half sB[128][72];   // 128x64 (+8 pad)
    __shared__ __align__(16) float  sC[64][72];

    const int tid = threadIdx.x;
    const int wid = tid >> 5;
    const int tile = blockIdx.x * 64;

#pragma unroll
    for (int s = 0; s < 8; s++) {
        int slot = tid + s * 256;               // 0..2047
        int row = slot >> 5;
        int c4  = slot & 31;
        int rg = tile + row;
        float4 v = make_float4(0.f, 0.f, 0.f, 0.f);
        if (rg < NN) v = *(const float4*)&x[(long)rg * FIN + c4 * 4];
        f4_to_h4(v, &sA[row][c4 * 4]);
    }
#pragma unroll
    for (int s = 0; s < 4; s++) {
        int slot = tid + s * 256;               // 0..1023 uint4
        int row = slot >> 3;                    // 0..127
        int c8  = slot & 7;
        *(uint4*)&sB[row][c8 * 8] = *(const uint4*)&g_w1h0[row * 64 + c8 * 8];
    }
    __syncthreads();

    const int row0 = (wid >> 1) * 16;
    const int col0 = (wid & 1) * 32;

    wmma::fragment<wmma::accumulator, 16, 16, 16, float> c0, c1;
    wmma::fill_fragment(c0, 0.f);
    wmma::fill_fragment(c1, 0.f);
#pragma unroll
    for (int k = 0; k < 8; k++) {
        wmma::fragment<wmma::matrix_a, 16, 16, 16, __half, wmma::row_major> a;
        wmma::fragment<wmma::matrix_b, 16, 16, 16, __half, wmma::row_major> b0, b1;
        wmma::load_matrix_sync(a, &sA[row0][k * 16], 136);
        wmma::load_matrix_sync(b0, &sB[k * 16][col0], 72);
        wmma::load_matrix_sync(b1, &sB[k * 16][col0 + 16], 72);
        wmma::mma_sync(c0, a, b0, c0);
        wmma::mma_sync(c1, a, b1, c1);
    }
    wmma::store_matrix_sync(&sC[row0][col0], c0, 72, wmma::mem_row_major);
    wmma::store_matrix_sync(&sC[row0][col0 + 16], c1, 72, wmma::mem_row_major);
    __syncthreads();

#pragma unroll
    for (int s = 0; s < 4; s++) {
        int slot = tid + s * 256;
        int row = slot >> 4;
        int c4  = slot & 15;
        float4 v = *(const float4*)&sC[row][c4 * 4];
        f4_to_h4(v, &g_y16[(long)(tile + row) * HH + c4 * 4]);
    }
}

// ---------------- fused layer: pull + z + z@W2 + h@W1next -------------------
// Block owns 64 nodes. Phase A: each warp pulls for 8 consecutive nodes,
// depositing z = fp16(relu((1+eps)y + agg + b1)) straight into the GEMM's
// sA tile. Phase B: wmma h = relu(z@W2+b2) -> g_hs16; optional phase C:
// y_next = h @ W1_next -> g_y16.
__global__ void __launch_bounds__(256) k_layer(const float* __restrict__ eps,
                                               int layer,
                                               const float* __restrict__ B1,
                                               const float* __restrict__ B2,
                                               int out_off, int has_next) {
    __shared__ __align__(16) __half sA[64][72];
    __shared__ __align__(16) __half sB[64][72];
    __shared__ __align__(16) float  sC[64][72];

    const int tid = threadIdx.x;
    const int wid = tid >> 5;
    const int lane = tid & 31;
    const int tile = blockIdx.x * 64;
    const int q = lane >> 3;      // neighbor slot 0..3
    const int c = lane & 7;       // 8-half chunk 0..7
    const float epsv = 1.0f + eps[layer];

    // Stage W2 while pulls are about to start (covered by the post-pull sync)
#pragma unroll
    for (int s = 0; s < 2; s++) {
        int slot = tid + s * 256;               // 0..511 uint4
        int row = slot >> 3;
        int c8  = slot & 7;
        *(uint4*)&sB[row][c8 * 8] = *(const uint4*)&g_w2h[layer][row * 64 + c8 * 8];
    }

    // Phase A: pull + fused z for this warp's 8 nodes
    for (int i = 0; i < 8; i++) {
        const int row = wid * 8 + i;
        const int node = tile + row;
        if (node < NN) {
            int beg = g_rowptr[node], end = g_rowptr[node + 1];
            float2 a0 = make_float2(0.f, 0.f), a1 = a0, a2 = a0, a3 = a0;
            for (int j = beg; j < end; j += 32) {
                int n = min(32, end - j);
                int idx = (lane < n) ? g_csr[j + lane] : 0;
                int t = 0;
                for (; t + 16 <= n; t += 16) {
                    int u0 = __shfl_sync(0xffffffffu, idx, t + 0 + q);
                    int u1 = __shfl_sync(0xffffffffu, idx, t + 4 + q);
                    int u2 = __shfl_sync(0xffffffffu, idx, t + 8 + q);
                    int u3 = __shfl_sync(0xffffffffu, idx, t + 12 + q);
                    uint4 r0 = *(const uint4*)&g_y16[(long)u0 * HH + c * 8];
                    uint4 r1 = *(const uint4*)&g_y16[(long)u1 * HH + c * 8];
                    uint4 r2 = *(const uint4*)&g_y16[(long)u2 * HH + c * 8];
                    uint4 r3 = *(const uint4*)&g_y16[(long)u3 * HH + c * 8];
                    acc8(r0, a0, a1, a2, a3);
                    acc8(r1, a0, a1, a2, a3);
                    acc8(r2, a0, a1, a2, a3);
                    acc8(r3, a0, a1, a2, a3);
                }
                for (; t < n; t += 4) {
                    int tt = t + q;
                    int sel = (tt < n) ? tt : t;
                    int u = __shfl_sync(0xffffffffu, idx, sel);
                    uint4 r = *(const uint4*)&g_y16[(long)u * HH + c * 8];
                    if (tt < n) acc8(r, a0, a1, a2, a3);
                }
            }
#pragma unroll
            for (int o = 8; o <= 16; o <<= 1) {
                a0.x += __shfl_xor_sync(0xffffffffu, a0.x, o);
                a0.y += __shfl_xor_sync(0xffffffffu, a0.y, o);
                a1.x += __shfl_xor_sync(0xffffffffu, a1.x, o);
                a1.y += __shfl_xor_sync(0xffffffffu, a1.y, o);
                a2.x += __shfl_xor_sync(0xffffffffu, a2.x, o);
                a2.y += __shfl_xor_sync(0xffffffffu, a2.y, o);
                a3.x += __shfl_xor_sync(0xffffffffu, a3.x, o);
                a3.y += __shfl_xor_sync(0xffffffffu, a3.y, o);
            }
            if (q == 0) {
                uint4 yr = *(const uint4*)&g_y16[(long)node * HH + c * 8];
                float2 y0 = __half22float2(*(const __half2*)&yr.x);
                float2 y1 = __half22float2(*(const __half2*)&yr.y);
                float2 y2 = __half22float2(*(const __half2*)&yr.z);
                float2 y3 = __half22float2(*(const __half2*)&yr.w);
                float4 ba = *(const float4*)&B1[c * 8];
                float4 bb = *(const float4*)&B1[c * 8 + 4];
                float z0 = fmaxf(epsv * y0.x + a0.x + ba.x, 0.f);
                float z1 = fmaxf(epsv * y0.y + a0.y + ba.y, 0.f);
                float z2 = fmaxf(epsv * y1.x + a1.x + ba.z, 0.f);
                float z3 = fmaxf(epsv * y1.y + a1.y + ba.w, 0.f);
                float z4 = fmaxf(epsv * y2.x + a2.x + bb.x, 0.f);
                float z5 = fmaxf(epsv * y2.y + a2.y + bb.y, 0.f);
                float z6 = fmaxf(epsv * y3.x + a3.x + bb.z, 0.f);
                float z7 = fmaxf(epsv * y3.y + a3.y + bb.w, 0.f);
                __half2 h0 = __floats2half2_rn(z0, z1);
                __half2 h1 = __floats2half2_rn(z2, z3);
                __half2 h2 = __floats2half2_rn(z4, z5);
                __half2 h3 = __floats2half2_rn(z6, z7);
                uint4 o;
                o.x = *(unsigned*)&h0; o.y = *(unsigned*)&h1;
                o.z = *(unsigned*)&h2; o.w = *(unsigned*)&h3;
                *(uint4*)&sA[row][c * 8] = o;
            }
        } else if (q == 0) {
            uint4 z = make_uint4(0u, 0u, 0u, 0u);
            *(uint4*)&sA[row][c * 8] = z;
        }
    }
    __syncthreads();

    // Phase B: h = relu(z @ W2 + b2)
    const int row0 = (wid >> 1) * 16;
    const int col0 = (wid & 1) * 32;

    wmma::fragment<wmma::accumulator, 16, 16, 16, float> c0, c1;
    wmma::fill_fragment(c0, 0.f);
    wmma::fill_fragment(c1, 0.f);
#pragma unroll
    for (int k = 0; k < 4; k++) {
        wmma::fragment<wmma::matrix_a, 16, 16, 16, __half, wmma::row_major> a;
        wmma::fragment<wmma::matrix_b, 16, 16, 16, __half, wmma::row_major> b0, b1;
        wmma::load_matrix_sync(a, &sA[row0][k * 16], 72);
        wmma::load_matrix_sync(b0, &sB[k * 16][col0], 72);
        wmma::load_matrix_sync(b1, &sB[k * 16][col0 + 16], 72);
        wmma::mma_sync(c0, a, b0, c0);
        wmma::mma_sync(c1, a, b1, c1);
    }
    wmma::store_matrix_sync(&sC[row0][col0], c0, 72, wmma::mem_row_major);
    wmma::store_matrix_sync(&sC[row0][col0 + 16], c1, 72, wmma::mem_row_major);
    __syncthreads();

    // Epilogue: h = relu(sC + b2) -> g_hs16 (+ sA/sB for phase C)
#pragma unroll
    for (int s = 0; s < 4; s++) {
        int slot = tid + s * 256;
        int row = slot >> 4;
        int c4  = slot & 15;
        float4 v = *(const float4*)&sC[row][c4 * 4];
        float4 bv = *(const float4*)&B2[c4 * 4];
        v.x = fmaxf(v.x + bv.x, 0.f);
        v.y = fmaxf(v.y + bv.y, 0.f);
        v.z = fmaxf(v.z + bv.z, 0.f);
        v.w = fmaxf(v.w + bv.w, 0.f);
        __half2 h01 = __floats2half2_rn(v.x, v.y);
        __half2 h23 = __floats2half2_rn(v.z, v.w);
        uint2 u;
        u.x = *(unsigned*)&h01;
        u.y = *(unsigned*)&h23;
        *(uint2*)&g_hs16[(long)(tile + row) * HS + out_off + c4 * 4] = u;
        *(uint2*)&sA[row][c4 * 4] = u;
    }
    if (!has_next) return;
#pragma unroll
    for (int s = 0; s < 2; s++) {
        int slot = tid + s * 256;
        int row = slot >> 3;
        int c8  = slot & 7;
        *(uint4*)&sB[row][c8 * 8] = *(const uint4*)&g_w1hn[layer][row * 64 + c8 * 8];
    }
    __syncthreads();

    // Phase C: y_next = h @ W1_next
    wmma::fill_fragment(c0, 0.f);
    wmma::fill_fragment(c1, 0.f);
#pragma unroll
    for (int k = 0; k < 4; k++) {
        wmma::fragment<wmma::matrix_a, 16, 16, 16, __half, wmma::row_major> a;
        wmma::fragment<wmma::matrix_b, 16, 16, 16, __half, wmma::row_major> b0, b1;
        wmma::load_matrix_sync(a, &sA[row0][k * 16], 72);
        wmma::load_matrix_sync(b0, &sB[k * 16][col0], 72);
        wmma::load_matrix_sync(b1, &sB[k * 16][col0 + 16], 72);
        wmma::mma_sync(c0, a, b0, c0);
        wmma::mma_sync(c1, a, b1, c1);
    }
    __syncthreads();     // all epilogue reads of sC are done
    wmma::store_matrix_sync(&sC[row0][col0], c0, 72, wmma::mem_row_major);
    wmma::store_matrix_sync(&sC[row0][col0 + 16], c1, 72, wmma::mem_row_major);
    __syncthreads();

#pragma unroll
    for (int s = 0; s < 4; s++) {
        int slot = tid + s * 256;
        int row = slot >> 4;
        int c4  = slot & 15;
        float4 v = *(const float4*)&sC[row][c4 * 4];
        f4_to_h4(v, &g_y16[(long)(tile + row) * HH + c4 * 4]);
    }
}

// ---------------- readout (binary-search offsets fused in) ------------------
__global__ void __launch_bounds__(192) k_readout(const void* __restrict__ batch,
                                                 const float* __restrict__ fc1w,
                                                 const float* __restrict__ fc1b,
                                                 const float* __restrict__ fc2w,
                                                 const float* __restrict__ fc2b,
                                                 float* __restrict__ out) {
    __shared__ float gv[GF];
    __shared__ float q[HH];
    __shared__ int bound[2];

    int g = blockIdx.x;
    int f = threadIdx.x;

    // threads 0/1 compute segment bounds via binary search (batch is sorted)
    if (f < 2) {
        int target = g + f;
        int lo = 0, hi = NN;
        if (target == NG) lo = NN;
        else {
            while (lo < hi) {
                int mid = (lo + hi) >> 1;
                if ((int)ld_idx(batch, mid) < target) lo = mid + 1; else hi = mid;
            }
        }
        bound[f] = lo;
    }
    __syncthreads();
    int n0 = bound[0], n1 = bound[1];

    float s = 0.f, m = -3.402823466e38f;
    for (int n = n0; n < n1; n++) {
        float v = __half2float(g_hs16[(long)n * HS + f]);
        s += v;
        m = fmaxf(m, v);
    }
    int cnt = n1 - n0;
    gv[f]       = s / fmaxf((float)cnt, 1.f);
    gv[192 + f] = m;
    gv[384 + f] = s;
    __syncthreads();

    if (f < HH) {
        float a = fc1b[f];
#pragma unroll 4
        for (int k = 0; k < GF; k++) a += gv[k] * fc1w[k * 64 + f];
        q[f] = fmaxf(a, 0.f);
    }
    __syncthreads();

    if (f < 2) {
        float a = fc2b[f];
#pragma unroll
        for (int k = 0; k < HH; k++) a += q[k] * fc2w[k * 2 + f];
        out[g * 2 + f] = 1.f / (1.f + expf(-a));
    }
}

// ---------------- launch ----------------------------------------------------
extern "C" void kernel_launch(void* const* d_in, const int* in_sizes, int n_in,
                              void* d_out, int out_size) {
    const float* x     = (const float*)d_in[0];
    const void*  edge  = d_in[1];
    const void*  batch = d_in[2];
    const float* w1[3] = {(const float*)d_in[3],  (const float*)d_in[7],  (const float*)d_in[11]};
    const float* b1[3] = {(const float*)d_in[4],  (const float*)d_in[8],  (const float*)d_in[12]};
    const float* w2[3] = {(const float*)d_in[5],  (const float*)d_in[9],  (const float*)d_in[13]};
    const float* b2[3] = {(const float*)d_in[6],  (const float*)d_in[10], (const float*)d_in[14]};
    const float* eps   = (const float*)d_in[15];
    const float* fc1w  = (const float*)d_in[16];
    const float* fc1b  = (const float*)d_in[17];
    const float* fc2w  = (const float*)d_in[18];
    const float* fc2b  = (const float*)d_in[19];

    // probe + zero degrees + weight conversion in one kernel
    k_prep<<<(NN + 255) / 256, 256>>>(edge, w1[0], w1[1], w1[2], w2[0], w2[1], w2[2]);

    // CSR build (once; reused by all 3 layers)
    k_deg<<<(NE + 255) / 256, 256>>>(edge);
    k_bsum<<<NSB, 256>>>();
    k_bscan<<<1, 128>>>();
    k_rowptr<<<NSB, 256>>>();
    k_fill<<<(NE + 255) / 256, 256>>>(edge);

    const int tile_grid = (NN + 63) / 64;

    // Layer 0 projection: y0 = x @ W1_0
    k_gemm1<<<tile_grid, 256>>>(x);

    for (int L = 0; L < 3; L++) {
        const int has_next = (L < 2) ? 1 : 0;
        k_layer<<<tile_grid, 256>>>(eps, L, b1[L], b2[L], L * 64, has_next);
    }

    k_readout<<<NG, 192>>>(batch, fc1w, fc1b, fc2w, fc2b, (float*)d_out);
}

// round 13
// speedup vs baseline: 1.0913x; 1.0913x over previous
#include <cuda_runtime.h>
#include <cuda_fp16.h>
#include <mma.h>
#include <math.h>

using namespace nvcuda;

// Problem constants (fixed shapes)
#define NN 100000
#define NE 1600000
#define NG 512
#define FIN 128
#define HH 64
#define HS 192   // 3*H concat width
#define GF 576   // 3*HS graph feature width

#define SCAN_CH 1024
#define NSB ((NN + SCAN_CH - 1) / SCAN_CH)   // 98 scan blocks
#define GEMM1_GRID ((NN + 63) / 64)          // 1563
#define DEG_GRID ((NE + 255) / 256)          // 6250

// ---------------- scratch (static device globals; no runtime alloc) -------
// +64-row padding lets GEMM tiles store unguarded past NN.
__device__ __align__(16) __half g_y16[(size_t)(NN + 64) * HH];   // projected feats
__device__ __align__(16) __half g_z16[(size_t)(NN + 64) * HH];   // z = relu((1+e)y+agg+b1)
__device__ __align__(16) __half g_hs16[(size_t)(NN + 64) * HS];  // concat outputs
__device__ __align__(16) __half g_w1h0[FIN * HH];     // W1 layer0 fp16
__device__ __align__(16) __half g_w1hn[2][HH * HH];   // W1 layers 1,2 fp16
__device__ __align__(16) __half g_w2h[3][HH * HH];    // W2 all layers fp16
__device__ __align__(16) int g_rowptr[NN + 4];
__device__ __align__(16) int g_cursor[NN + 4];
__device__ int g_csr[NE];
__device__ int g_bsum[NSB];
__device__ int g_boff[NSB + 1];
__device__ int g_ticket;
__device__ int g_is64;

// ---------------- index dtype handling -------------------------------------
__device__ __forceinline__ long ld_idx(const void* p, long i) {
    if (g_is64) return (long)((const long long*)p)[i];
    return (long)((const int*)p)[i];
}

// ---------------- prep: dtype probe + zero degrees + weight fp16 convert ---
__global__ void k_prep(const void* edge,
                       const float* __restrict__ w10, const float* __restrict__ w11,
                       const float* __restrict__ w12, const float* __restrict__ w20,
                       const float* __restrict__ w21, const float* __restrict__ w22) {
    int i = blockIdx.x * 256 + threadIdx.x;
    if (blockIdx.x == 0 && threadIdx.x < 32) {
        // int64 indices < 2^31 => every odd 32-bit word is zero.
        const int* p = (const int*)edge;
        int nz = (p[2 * threadIdx.x + 1] != 0) ? 1 : 0;
        unsigned m = __ballot_sync(0xffffffffu, nz);
        if (threadIdx.x == 0) g_is64 = (m == 0) ? 1 : 0;
        if (threadIdx.x == 1) g_ticket = 0;
    }
    if (i < NN) g_cursor[i] = 0;
    if (i < 8192)       g_w1h0[i]            = __float2half_rn(w10[i]);
    else if (i < 12288) g_w1hn[0][i - 8192]  = __float2half_rn(w11[i - 8192]);
    else if (i < 16384) g_w1hn[1][i - 12288] = __float2half_rn(w12[i - 12288]);
    else if (i < 20480) g_w2h[0][i - 16384]  = __float2half_rn(w20[i - 16384]);
    else if (i < 24576) g_w2h[1][i - 20480]  = __float2half_rn(w21[i - 20480]);
    else if (i < 28672) g_w2h[2][i - 24576]  = __float2half_rn(w22[i - 24576]);
}

// ---------------- helpers ---------------------------------------------------
__device__ __forceinline__ void f4_to_h4(const float4& v, __half* dst) {
    __half2 h01 = __floats2half2_rn(v.x, v.y);
    __half2 h23 = __floats2half2_rn(v.z, v.w);
    uint2 u;
    u.x = *(unsigned*)&h01;
    u.y = *(unsigned*)&h23;
    *(uint2*)dst = u;
}

__device__ __forceinline__ void acc8(const uint4& r, float2& a0, float2& a1,
                                     float2& a2, float2& a3) {
    float2 p;
    p = __half22float2(*(const __half2*)&r.x); a0.x += p.x; a0.y += p.y;
    p = __half22float2(*(const __half2*)&r.y); a1.x += p.x; a1.y += p.y;
    p = __half22float2(*(const __half2*)&r.z); a2.x += p.x; a2.y += p.y;
    p = __half22float2(*(const __half2*)&r.w); a3.x += p.x; a3.y += p.y;
}

// ---------------- k_par1: gemm1 (blocks < GEMM1_GRID) ∥ deg (rest) ---------
// gemm1: y0 = x @ W1_0 via tensor cores; deg: degree histogram atomics.
// Independent work co-scheduled in one launch for free overlap.
union G1Smem {
    __half a[64][136];   // 17408 B — staged x tile
    float  c[64][72];    // 18432 B — accum tile (after mma, aliased)
};

__global__ void __launch_bounds__(256) k_par1(const float* __restrict__ x,
                                              const void* __restrict__ edge) {
    __shared__ __align__(16) G1Smem sU;
    __shared__ __align__(16) __half sB[128][72];

    const int tid = threadIdx.x;

    if (blockIdx.x >= GEMM1_GRID) {
        // ---- degree histogram branch ----
        long e = (long)(blockIdx.x - GEMM1_GRID) * 256 + tid;
        if (e < NE) {
            int d = (int)ld_idx(edge, (long)NE + e);
            atomicAdd(&g_cursor[d], 1);
        }
        return;
    }

    // ---- gemm1 branch ----
    const int wid = tid >> 5;
    const int tile = blockIdx.x * 64;

#pragma unroll
    for (int s = 0; s < 8; s++) {
        int slot = tid + s * 256;               // 0..2047
        int row = slot >> 5;
        int c4  = slot & 31;
        int rg = tile + row;
        float4 v = make_float4(0.f, 0.f, 0.f, 0.f);
        if (rg < NN) v = *(const float4*)&x[(long)rg * FIN + c4 * 4];
        f4_to_h4(v, &sU.a[row][c4 * 4]);
    }
#pragma unroll
    for (int s = 0; s < 4; s++) {
        int slot = tid + s * 256;               // 0..1023 uint4
        int row = slot >> 3;                    // 0..127
        int c8  = slot & 7;
        *(uint4*)&sB[row][c8 * 8] = *(const uint4*)&g_w1h0[row * 64 + c8 * 8];
    }
    __syncthreads();

    const int row0 = (wid >> 1) * 16;
    const int col0 = (wid & 1) * 32;

    wmma::fragment<wmma::accumulator, 16, 16, 16, float> c0, c1;
    wmma::fill_fragment(c0, 0.f);
    wmma::fill_fragment(c1, 0.f);
#pragma unroll
    for (int k = 0; k < 8; k++) {
        wmma::fragment<wmma::matrix_a, 16, 16, 16, __half, wmma::row_major> a;
        wmma::fragment<wmma::matrix_b, 16, 16, 16, __half, wmma::row_major> b0, b1;
        wmma::load_matrix_sync(a, &sU.a[row0][k * 16], 136);
        wmma::load_matrix_sync(b0, &sB[k * 16][col0], 72);
        wmma::load_matrix_sync(b1, &sB[k * 16][col0 + 16], 72);
        wmma::mma_sync(c0, a, b0, c0);
        wmma::mma_sync(c1, a, b1, c1);
    }
    __syncthreads();            // all warps done reading sU.a before aliasing
    wmma::store_matrix_sync(&sU.c[row0][col0], c0, 72, wmma::mem_row_major);
    wmma::store_matrix_sync(&sU.c[row0][col0 + 16], c1, 72, wmma::mem_row_major);
    __syncthreads();

#pragma unroll
    for (int s = 0; s < 4; s++) {
        int slot = tid + s * 256;
        int row = slot >> 4;
        int c4  = slot & 15;
        float4 v = *(const float4*)&sU.c[row][c4 * 4];
        f4_to_h4(v, &g_y16[(long)(tile + row) * HH + c4 * 4]);
    }
}

// ---------------- CSR scan (bsum + last-block bscan fused) ------------------
__global__ void __launch_bounds__(256) k_bsum() {
    __shared__ int ws[8];
    __shared__ int sScan[128];
    __shared__ int sIsLast;
    const int b = blockIdx.x, t = threadIdx.x;
    const int base = b * SCAN_CH + t * 4;
    int s = 0;
    if (base < NN) {
        int4 v = *(const int4*)&g_cursor[base];
        s = (v.x + v.y) + (v.z + v.w);
    }
#pragma unroll
    for (int o = 16; o > 0; o >>= 1) s += __shfl_down_sync(0xffffffffu, s, o);
    if ((t & 31) == 0) ws[t >> 5] = s;
    __syncthreads();
    if (t < 8) {
        int v = ws[t];
#pragma unroll
        for (int o = 4; o > 0; o >>= 1) v += __shfl_down_sync(0xffu, v, o);
        if (t == 0) {
            g_bsum[b] = v;
            __threadfence();
            int tk = atomicAdd(&g_ticket, 1);
            sIsLast = (tk == NSB - 1) ? 1 : 0;
        }
    }
    __syncthreads();
    if (sIsLast) {
        // last-arriving block scans the 98 partials
        int v = (t < NSB) ? g_bsum[t] : 0;
        if (t < 128) sScan[t] = v;
        __syncthreads();
        for (int d = 1; d < 128; d <<= 1) {
            int u = (t >= d && t < 128) ? sScan[t - d] : 0;
            __syncthreads();
            if (t < 128) sScan[t] += u;
            __syncthreads();
        }
        if (t < 128) {
            g_boff[t] = (t == 0) ? 0 : sScan[t - 1];
            if (t == NSB - 1) g_rowptr[NN] = sScan[t];
        }
    }
}

__global__ void __launch_bounds__(256) k_rowptr() {
    __shared__ int s[256];
    const int b = blockIdx.x, t = threadIdx.x;
    const int base = b * SCAN_CH + t * 4;
    int d0 = 0, d1 = 0, d2 = 0, d3 = 0;
    if (base < NN) {
        int4 v = *(const int4*)&g_cursor[base];
        d0 = v.x; d1 = v.y; d2 = v.z; d3 = v.w;
    }
    s[t] = d0 + d1 + d2 + d3;
    __syncthreads();
#pragma unroll
    for (int d = 1; d < 256; d <<= 1) {
        int u = (t >= d) ? s[t - d] : 0;
        __syncthreads();
        s[t] += u;
        __syncthreads();
    }
    int off = g_boff[b] + ((t == 0) ? 0 : s[t - 1]);
    if (base < NN) {
        int4 r;
        r.x = off;
        r.y = off + d0;
        r.z = off + d0 + d1;
        r.w = off + d0 + d1 + d2;
        *(int4*)&g_rowptr[base] = r;
        *(int4*)&g_cursor[base] = r;
    }
}

__global__ void k_fill(const void* __restrict__ edge) {
    long e = (long)blockIdx.x * 256 + threadIdx.x;
    if (e < NE) {
        int s = (int)ld_idx(edge, e);
        int d = (int)ld_idx(edge, (long)NE + e);
        int pos = atomicAdd(&g_cursor[d], 1);
        g_csr[pos] = s;
    }
}

// ---------------- pull + fused z epilogue -----------------------------------
// One warp/node; lane = 8*q + c. Each lane loads 8 halves of neighbor t+q:
// one warp-wide load covers 4 neighbors. fp32 accumulation. After the
// cross-quad reduction, q==0 lanes read their own y16 row and write
// z = fp16(relu((1+eps)*y + agg + b1)) — gemm2 then just copies z16.
__global__ void __launch_bounds__(256) k_pull64(const float* __restrict__ eps,
                                                int layer,
                                                const float* __restrict__ B1) {
    int node = (blockIdx.x * 256 + threadIdx.x) >> 5;
    int lane = threadIdx.x & 31;
    if (node >= NN) return;
    const int q = lane >> 3;      // neighbor slot 0..3
    const int c = lane & 7;       // 8-half chunk 0..7
    int beg = g_rowptr[node], end = g_rowptr[node + 1];

    float2 a0 = make_float2(0.f, 0.f), a1 = a0, a2 = a0, a3 = a0;
    for (int j = beg; j < end; j += 32) {
        int n = min(32, end - j);
        int idx = (lane < n) ? g_csr[j + lane] : 0;
        int t = 0;
        for (; t + 16 <= n; t += 16) {
            int u0 = __shfl_sync(0xffffffffu, idx, t + 0 + q);
            int u1 = __shfl_sync(0xffffffffu, idx, t + 4 + q);
            int u2 = __shfl_sync(0xffffffffu, idx, t + 8 + q);
            int u3 = __shfl_sync(0xffffffffu, idx, t + 12 + q);
            uint4 r0 = *(const uint4*)&g_y16[(long)u0 * HH + c * 8];
            uint4 r1 = *(const uint4*)&g_y16[(long)u1 * HH + c * 8];
            uint4 r2 = *(const uint4*)&g_y16[(long)u2 * HH + c * 8];
            uint4 r3 = *(const uint4*)&g_y16[(long)u3 * HH + c * 8];
            acc8(r0, a0, a1, a2, a3);
            acc8(r1, a0, a1, a2, a3);
            acc8(r2, a0, a1, a2, a3);
            acc8(r3, a0, a1, a2, a3);
        }
        for (; t < n; t += 4) {
            int tt = t + q;
            int sel = (tt < n) ? tt : t;
            int u = __shfl_sync(0xffffffffu, idx, sel);
            uint4 r = *(const uint4*)&g_y16[(long)u * HH + c * 8];
            if (tt < n) acc8(r, a0, a1, a2, a3);
        }
    }
#pragma unroll
    for (int o = 8; o <= 16; o <<= 1) {
        a0.x += __shfl_xor_sync(0xffffffffu, a0.x, o);
        a0.y += __shfl_xor_sync(0xffffffffu, a0.y, o);
        a1.x += __shfl_xor_sync(0xffffffffu, a1.x, o);
        a1.y += __shfl_xor_sync(0xffffffffu, a1.y, o);
        a2.x += __shfl_xor_sync(0xffffffffu, a2.x, o);
        a2.y += __shfl_xor_sync(0xffffffffu, a2.y, o);
        a3.x += __shfl_xor_sync(0xffffffffu, a3.x, o);
        a3.y += __shfl_xor_sync(0xffffffffu, a3.y, o);
    }
    if (q == 0) {
        const float epsv = 1.0f + eps[layer];
        uint4 yr = *(const uint4*)&g_y16[(long)node * HH + c * 8];
        float2 y0 = __half22float2(*(const __half2*)&yr.x);
        float2 y1 = __half22float2(*(const __half2*)&yr.y);
        float2 y2 = __half22float2(*(const __half2*)&yr.z);
        float2 y3 = __half22float2(*(const __half2*)&yr.w);
        float4 ba = *(const float4*)&B1[c * 8];
        float4 bb = *(const float4*)&B1[c * 8 + 4];
        float z0 = fmaxf(epsv * y0.x + a0.x + ba.x, 0.f);
        float z1 = fmaxf(epsv * y0.y + a0.y + ba.y, 0.f);
        float z2 = fmaxf(epsv * y1.x + a1.x + ba.z, 0.f);
        float z3 = fmaxf(epsv * y1.y + a1.y + ba.w, 0.f);
        float z4 = fmaxf(epsv * y2.x + a2.x + bb.x, 0.f);
        float z5 = fmaxf(epsv * y2.y + a2.y + bb.y, 0.f);
        float z6 = fmaxf(epsv * y3.x + a3.x + bb.z, 0.f);
        float z7 = fmaxf(epsv * y3.y + a3.y + bb.w, 0.f);
        __half2 h0 = __floats2half2_rn(z0, z1);
        __half2 h1 = __floats2half2_rn(z2, z3);
        __half2 h2 = __floats2half2_rn(z4, z5);
        __half2 h3 = __floats2half2_rn(z6, z7);
        uint4 o;
        o.x = *(unsigned*)&h0; o.y = *(unsigned*)&h1;
        o.z = *(unsigned*)&h2; o.w = *(unsigned*)&h3;
        *(uint4*)&g_z16[(long)node * HH + c * 8] = o;
    }
}

// ---------------- GEMM2: h = relu(z16@W2+b2); opt y_next = h @ W1_next ------
__global__ void __launch_bounds__(256) k_gemm2(int layer,
                                               const float* __restrict__ B2,
                                               int out_off, int has_next) {
    __shared__ __align__(16) __half sA[64][72];
    __shared__ __align__(16) __half sB[64][72];
    __shared__ __align__(16) float  sC[64][72];

    const int tid = threadIdx.x;
    const int wid = tid >> 5;
    const int tile = blockIdx.x * 64;

    // Stage z16 and W2 (pure fp16 copies)
#pragma unroll
    for (int s = 0; s < 2; s++) {
        int slot = tid + s * 256;               // 0..511 uint4
        int row = slot >> 3;
        int c8  = slot & 7;
        *(uint4*)&sA[row][c8 * 8] = *(const uint4*)&g_z16[(long)(tile + row) * HH + c8 * 8];
        *(uint4*)&sB[row][c8 * 8] = *(const uint4*)&g_w2h[layer][row * 64 + c8 * 8];
    }
    __syncthreads();

    const int row0 = (wid >> 1) * 16;
    const int col0 = (wid & 1) * 32;

    wmma::fragment<wmma::accumulator, 16, 16, 16, float> c0, c1;
    wmma::fill_fragment(c0, 0.f);
    wmma::fill_fragment(c1, 0.f);
#pragma unroll
    for (int k = 0; k < 4; k++) {
        wmma::fragment<wmma::matrix_a, 16, 16, 16, __half, wmma::row_major> a;
        wmma::fragment<wmma::matrix_b, 16, 16, 16, __half, wmma::row_major> b0, b1;
        wmma::load_matrix_sync(a, &sA[row0][k * 16], 72);
        wmma::load_matrix_sync(b0, &sB[k * 16][col0], 72);
        wmma::load_matrix_sync(b1, &sB[k * 16][col0 + 16], 72);
        wmma::mma_sync(c0, a, b0, c0);
        wmma::mma_sync(c1, a, b1, c1);
    }
    wmma::store_matrix_sync(&sC[row0][col0], c0, 72, wmma::mem_row_major);
    wmma::store_matrix_sync(&sC[row0][col0 + 16], c1, 72, wmma::mem_row_major);
    __syncthreads();

    // Epilogue: h = relu(sC + b2) -> g_hs16 (+ sA/sB for phase 2)
#pragma unroll
    for (int s = 0; s < 4; s++) {
        int slot = tid + s * 256;
        int row = slot >> 4;
        int c4  = slot & 15;
        float4 v = *(const float4*)&sC[row][c4 * 4];
        float4 bv = *(const float4*)&B2[c4 * 4];
        v.x = fmaxf(v.x + bv.x, 0.f);
        v.y = fmaxf(v.y + bv.y, 0.f);
        v.z = fmaxf(v.z + bv.z, 0.f);
        v.w = fmaxf(v.w + bv.w, 0.f);
        __half2 h01 = __floats2half2_rn(v.x, v.y);
        __half2 h23 = __floats2half2_rn(v.z, v.w);
        uint2 u;
        u.x = *(unsigned*)&h01;
        u.y = *(unsigned*)&h23;
        *(uint2*)&g_hs16[(long)(tile + row) * HS + out_off + c4 * 4] = u;
        *(uint2*)&sA[row][c4 * 4] = u;
    }
    if (!has_next) return;
#pragma unroll
    for (int s = 0; s < 2; s++) {
        int slot = tid + s * 256;
        int row = slot >> 3;
        int c8  = slot & 7;
        *(uint4*)&sB[row][c8 * 8] = *(const uint4*)&g_w1hn[layer][row * 64 + c8 * 8];
    }
    __syncthreads();

    // Phase 2: y_next = h @ W1_next
    wmma::fill_fragment(c0, 0.f);
    wmma::fill_fragment(c1, 0.f);
#pragma unroll
    for (int k = 0; k < 4; k++) {
        wmma::fragment<wmma::matrix_a, 16, 16, 16, __half, wmma::row_major> a;
        wmma::fragment<wmma::matrix_b, 16, 16, 16, __half, wmma::row_major> b0, b1;
        wmma::load_matrix_sync(a, &sA[row0][k * 16], 72);
        wmma::load_matrix_sync(b0, &sB[k * 16][col0], 72);
        wmma::load_matrix_sync(b1, &sB[k * 16][col0 + 16], 72);
        wmma::mma_sync(c0, a, b0, c0);
        wmma::mma_sync(c1, a, b1, c1);
    }
    __syncthreads();     // all epilogue reads of sC are done
    wmma::store_matrix_sync(&sC[row0][col0], c0, 72, wmma::mem_row_major);
    wmma::store_matrix_sync(&sC[row0][col0 + 16], c1, 72, wmma::mem_row_major);
    __syncthreads();

#pragma unroll
    for (int s = 0; s < 4; s++) {
        int slot = tid + s * 256;
        int row = slot >> 4;
        int c4  = slot & 15;
        float4 v = *(const float4*)&sC[row][c4 * 4];
        f4_to_h4(v, &g_y16[(long)(tile + row) * HH + c4 * 4]);
    }
}

// ---------------- readout (binary-search offsets fused in) ------------------
__global__ void __launch_bounds__(192) k_readout(const void* __restrict__ batch,
                                                 const float* __restrict__ fc1w,
                                                 const float* __restrict__ fc1b,
                                                 const float* __restrict__ fc2w,
                                                 const float* __restrict__ fc2b,
                                                 float* __restrict__ out) {
    __shared__ float gv[GF];
    __shared__ float q[HH];
    __shared__ int bound[2];

    int g = blockIdx.x;
    int f = threadIdx.x;

    // threads 0/1 compute segment bounds via binary search (batch is sorted)
    if (f < 2) {
        int target = g + f;
        int lo = 0, hi = NN;
        if (target == NG) lo = NN;
        else {
            while (lo < hi) {
                int mid = (lo + hi) >> 1;
                if ((int)ld_idx(batch, mid) < target) lo = mid + 1; else hi = mid;
            }
        }
        bound[f] = lo;
    }
    __syncthreads();
    int n0 = bound[0], n1 = bound[1];

    float s = 0.f, m = -3.402823466e38f;
    for (int n = n0; n < n1; n++) {
        float v = __half2float(g_hs16[(long)n * HS + f]);
        s += v;
        m = fmaxf(m, v);
    }
    int cnt = n1 - n0;
    gv[f]       = s / fmaxf((float)cnt, 1.f);
    gv[192 + f] = m;
    gv[384 + f] = s;
    __syncthreads();

    if (f < HH) {
        float a = fc1b[f];
#pragma unroll 4
        for (int k = 0; k < GF; k++) a += gv[k] * fc1w[k * 64 + f];
        q[f] = fmaxf(a, 0.f);
    }
    __syncthreads();

    if (f < 2) {
        float a = fc2b[f];
#pragma unroll
        for (int k = 0; k < HH; k++) a += q[k] * fc2w[k * 2 + f];
        out[g * 2 + f] = 1.f / (1.f + expf(-a));
    }
}

// ---------------- launch ----------------------------------------------------
extern "C" void kernel_launch(void* const* d_in, const int* in_sizes, int n_in,
                              void* d_out, int out_size) {
    const float* x     = (const float*)d_in[0];
    const void*  edge  = d_in[1];
    const void*  batch = d_in[2];
    const float* w1[3] = {(const float*)d_in[3],  (const float*)d_in[7],  (const float*)d_in[11]};
    const float* b1[3] = {(const float*)d_in[4],  (const float*)d_in[8],  (const float*)d_in[12]};
    const float* w2[3] = {(const float*)d_in[5],  (const float*)d_in[9],  (const float*)d_in[13]};
    const float* b2[3] = {(const float*)d_in[6],  (const float*)d_in[10], (const float*)d_in[14]};
    const float* eps   = (const float*)d_in[15];
    const float* fc1w  = (const float*)d_in[16];
    const float* fc1b  = (const float*)d_in[17];
    const float* fc2w  = (const float*)d_in[18];
    const float* fc2b  = (const float*)d_in[19];

    // probe + zero degrees + ticket + weight conversion
    k_prep<<<(NN + 255) / 256, 256>>>(edge, w1[0], w1[1], w1[2], w2[0], w2[1], w2[2]);

    // gemm1 (y0 = x @ W1_0) co-scheduled with degree histogram
    k_par1<<<GEMM1_GRID + DEG_GRID, 256>>>(x, edge);

    // CSR scan + fill
    k_bsum<<<NSB, 256>>>();
    k_rowptr<<<NSB, 256>>>();
    k_fill<<<DEG_GRID, 256>>>(edge);

    const int pull_grid = (NN + 7) / 8;
    for (int L = 0; L < 3; L++) {
        k_pull64<<<pull_grid, 256>>>(eps, L, b1[L]);
        const int has_next = (L < 2) ? 1 : 0;
        k_gemm2<<<GEMM1_GRID, 256>>>(L, b2[L], L * 64, has_next);
    }

    k_readout<<<NG, 192>>>(batch, fc1w, fc1b, fc2w, fc2b, (float*)d_out);
}

// round 14
// speedup vs baseline: 1.0941x; 1.0026x over previous
#include <cuda_runtime.h>
#include <cuda_fp16.h>
#include <mma.h>
#include <math.h>

using namespace nvcuda;

// Problem constants (fixed shapes)
#define NN 100000
#define NE 1600000
#define NG 512
#define FIN 128
#define HH 64
#define HS 192   // 3*H concat width
#define GF 576   // 3*HS graph feature width

#define SCAN_CH 1024
#define NSB ((NN + SCAN_CH - 1) / SCAN_CH)   // 98 scan blocks (<= 148 SMs: co-resident)
#define GEMM1_GRID ((NN + 63) / 64)          // 1563
#define DEG_GRID ((NE + 255) / 256)          // 6250

// ---------------- scratch (static device globals; no runtime alloc) -------
// +64-row padding lets GEMM tiles store unguarded past NN.
__device__ __align__(16) __half g_y16[(size_t)(NN + 64) * HH];   // projected feats
__device__ __align__(16) __half g_z16[(size_t)(NN + 64) * HH];   // z = relu((1+e)y+agg+b1)
__device__ __align__(16) __half g_hs16[(size_t)(NN + 64) * HS];  // concat outputs
__device__ __align__(16) __half g_w1h0[FIN * HH];     // W1 layer0 fp16
__device__ __align__(16) __half g_w1hn[2][HH * HH];   // W1 layers 1,2 fp16
__device__ __align__(16) __half g_w2h[3][HH * HH];    // W2 all layers fp16
__device__ __align__(16) int g_rowptr[NN + 4];
__device__ __align__(16) int g_cursor[NN + 4];
__device__ int g_csr[NE];
__device__ int g_bsum[NSB];
__device__ int g_boff[NSB + 1];
__device__ int g_ticket;
__device__ volatile int g_done;
__device__ int g_is64;

// ---------------- index dtype handling -------------------------------------
__device__ __forceinline__ long ld_idx(const void* p, long i) {
    if (g_is64) return (long)((const long long*)p)[i];
    return (long)((const int*)p)[i];
}

// ---------------- prep: dtype probe + zero degrees + weight fp16 convert ---
__global__ void k_prep(const void* edge,
                       const float* __restrict__ w10, const float* __restrict__ w11,
                       const float* __restrict__ w12, const float* __restrict__ w20,
                       const float* __restrict__ w21, const float* __restrict__ w22) {
    int i = blockIdx.x * 256 + threadIdx.x;
    if (blockIdx.x == 0 && threadIdx.x < 32) {
        // int64 indices < 2^31 => every odd 32-bit word is zero.
        const int* p = (const int*)edge;
        int nz = (p[2 * threadIdx.x + 1] != 0) ? 1 : 0;
        unsigned m = __ballot_sync(0xffffffffu, nz);
        if (threadIdx.x == 0) g_is64 = (m == 0) ? 1 : 0;
        if (threadIdx.x == 1) g_ticket = 0;
        if (threadIdx.x == 2) g_done = 0;
    }
    if (i < NN) g_cursor[i] = 0;
    if (i < 8192)       g_w1h0[i]            = __float2half_rn(w10[i]);
    else if (i < 12288) g_w1hn[0][i - 8192]  = __float2half_rn(w11[i - 8192]);
    else if (i < 16384) g_w1hn[1][i - 12288] = __float2half_rn(w12[i - 12288]);
    else if (i < 20480) g_w2h[0][i - 16384]  = __float2half_rn(w20[i - 16384]);
    else if (i < 24576) g_w2h[1][i - 20480]  = __float2half_rn(w21[i - 20480]);
    else if (i < 28672) g_w2h[2][i - 24576]  = __float2half_rn(w22[i - 24576]);
}

// ---------------- helpers ---------------------------------------------------
__device__ __forceinline__ void f4_to_h4(const float4& v, __half* dst) {
    __half2 h01 = __floats2half2_rn(v.x, v.y);
    __half2 h23 = __floats2half2_rn(v.z, v.w);
    uint2 u;
    u.x = *(unsigned*)&h01;
    u.y = *(unsigned*)&h23;
    *(uint2*)dst = u;
}

__device__ __forceinline__ void acc8(const uint4& r, float2& a0, float2& a1,
                                     float2& a2, float2& a3) {
    float2 p;
    p = __half22float2(*(const __half2*)&r.x); a0.x += p.x; a0.y += p.y;
    p = __half22float2(*(const __half2*)&r.y); a1.x += p.x; a1.y += p.y;
    p = __half22float2(*(const __half2*)&r.z); a2.x += p.x; a2.y += p.y;
    p = __half22float2(*(const __half2*)&r.w); a3.x += p.x; a3.y += p.y;
}

// ---------------- k_par1: gemm1 (blocks < GEMM1_GRID) ∥ deg (rest) ---------
// gemm1: y0 = x @ W1_0 via tensor cores; deg: degree histogram atomics.
union G1Smem {
    __half a[64][136];   // 17408 B — staged x tile
    float  c[64][72];    // 18432 B — accum tile (after mma, aliased)
};

__global__ void __launch_bounds__(256) k_par1(const float* __restrict__ x,
                                              const void* __restrict__ edge) {
    __shared__ __align__(16) G1Smem sU;
    __shared__ __align__(16) __half sB[128][72];

    const int tid = threadIdx.x;

    if (blockIdx.x >= GEMM1_GRID) {
        // ---- degree histogram branch ----
        long e = (long)(blockIdx.x - GEMM1_GRID) * 256 + tid;
        if (e < NE) {
            int d = (int)ld_idx(edge, (long)NE + e);
            atomicAdd(&g_cursor[d], 1);
        }
        return;
    }

    // ---- gemm1 branch ----
    const int wid = tid >> 5;
    const int tile = blockIdx.x * 64;

#pragma unroll
    for (int s = 0; s < 8; s++) {
        int slot = tid + s * 256;               // 0..2047
        int row = slot >> 5;
        int c4  = slot & 31;
        int rg = tile + row;
        float4 v = make_float4(0.f, 0.f, 0.f, 0.f);
        if (rg < NN) v = *(const float4*)&x[(long)rg * FIN + c4 * 4];
        f4_to_h4(v, &sU.a[row][c4 * 4]);
    }
#pragma unroll
    for (int s = 0; s < 4; s++) {
        int slot = tid + s * 256;               // 0..1023 uint4
        int row = slot >> 3;                    // 0..127
        int c8  = slot & 7;
        *(uint4*)&sB[row][c8 * 8] = *(const uint4*)&g_w1h0[row * 64 + c8 * 8];
    }
    __syncthreads();

    const int row0 = (wid >> 1) * 16;
    const int col0 = (wid & 1) * 32;

    wmma::fragment<wmma::accumulator, 16, 16, 16, float> c0, c1;
    wmma::fill_fragment(c0, 0.f);
    wmma::fill_fragment(c1, 0.f);
#pragma unroll
    for (int k = 0; k < 8; k++) {
        wmma::fragment<wmma::matrix_a, 16, 16, 16, __half, wmma::row_major> a;
        wmma::fragment<wmma::matrix_b, 16, 16, 16, __half, wmma::row_major> b0, b1;
        wmma::load_matrix_sync(a, &sU.a[row0][k * 16], 136);
        wmma::load_matrix_sync(b0, &sB[k * 16][col0], 72);
        wmma::load_matrix_sync(b1, &sB[k * 16][col0 + 16], 72);
        wmma::mma_sync(c0, a, b0, c0);
        wmma::mma_sync(c1, a, b1, c1);
    }
    __syncthreads();            // all warps done reading sU.a before aliasing
    wmma::store_matrix_sync(&sU.c[row0][col0], c0, 72, wmma::mem_row_major);
    wmma::store_matrix_sync(&sU.c[row0][col0 + 16], c1, 72, wmma::mem_row_major);
    __syncthreads();

#pragma unroll
    for (int s = 0; s < 4; s++) {
        int slot = tid + s * 256;
        int row = slot >> 4;
        int c4  = slot & 15;
        float4 v = *(const float4*)&sU.c[row][c4 * 4];
        f4_to_h4(v, &g_y16[(long)(tile + row) * HH + c4 * 4]);
    }
}

// ---------------- k_csr: full CSR scan in ONE kernel ------------------------
// 98 blocks (co-resident). Phase 1: block-sum of the 1024 degrees (held in
// registers), ticket; last block scans the partials -> g_boff, raises g_done.
// All blocks spin on g_done, then Phase 2: in-block exclusive scan writes
// rowptr + cursor without rereading the degree array.
__global__ void __launch_bounds__(256) k_csr() {
    __shared__ int ws[8];
    __shared__ int sScan[256];
    __shared__ int sIsLast;
    const int b = blockIdx.x, t = threadIdx.x;
    const int base = b * SCAN_CH + t * 4;

    int d0 = 0, d1 = 0, d2 = 0, d3 = 0;
    if (base < NN) {
        int4 v = *(const int4*)&g_cursor[base];
        d0 = v.x; d1 = v.y; d2 = v.z; d3 = v.w;
    }
    int mysum = d0 + d1 + d2 + d3;

    // Phase 1: block reduction -> g_bsum[b]
    int s = mysum;
#pragma unroll
    for (int o = 16; o > 0; o >>= 1) s += __shfl_down_sync(0xffffffffu, s, o);
    if ((t & 31) == 0) ws[t >> 5] = s;
    __syncthreads();
    if (t < 8) {
        int v = ws[t];
#pragma unroll
        for (int o = 4; o > 0; o >>= 1) v += __shfl_down_sync(0xffu, v, o);
        if (t == 0) {
            g_bsum[b] = v;
            __threadfence();
            int tk = atomicAdd(&g_ticket, 1);
            sIsLast = (tk == NSB - 1) ? 1 : 0;
        }
    }
    __syncthreads();

    if (sIsLast) {
        // last-arriving block scans the 98 partials -> g_boff
        int v = (t < NSB) ? g_bsum[t] : 0;
        if (t < 128) sScan[t] = v;
        __syncthreads();
        for (int d = 1; d < 128; d <<= 1) {
            int u = (t >= d && t < 128) ? sScan[t - d] : 0;
            __syncthreads();
            if (t < 128) sScan[t] += u;
            __syncthreads();
        }
        if (t < 128) {
            g_boff[t] = (t == 0) ? 0 : sScan[t - 1];
            if (t == NSB - 1) g_rowptr[NN] = sScan[t];
        }
        __syncthreads();
        if (t == 0) {
            __threadfence();
            g_done = 1;
        }
    }

    // all blocks wait for g_boff
    if (t == 0) {
        while (g_done == 0) { }
        sIsLast = -1;    // reuse as arrival marker (any write suffices)
    }
    __syncthreads();
    __threadfence();     // acquire: make g_boff writes visible

    // Phase 2: in-block exclusive scan of register-held degrees
    sScan[t] = mysum;
    __syncthreads();
#pragma unroll
    for (int d = 1; d < 256; d <<= 1) {
        int u = (t >= d) ? sScan[t - d] : 0;
        __syncthreads();
        sScan[t] += u;
        __syncthreads();
    }
    int off = g_boff[b] + ((t == 0) ? 0 : sScan[t - 1]);
    if (base < NN) {
        int4 r;
        r.x = off;
        r.y = off + d0;
        r.z = off + d0 + d1;
        r.w = off + d0 + d1 + d2;
        *(int4*)&g_rowptr[base] = r;
        *(int4*)&g_cursor[base] = r;
    }
}

__global__ void k_fill(const void* __restrict__ edge) {
    long e = (long)blockIdx.x * 256 + threadIdx.x;
    if (e < NE) {
        int s = (int)ld_idx(edge, e);
        int d = (int)ld_idx(edge, (long)NE + e);
        int pos = atomicAdd(&g_cursor[d], 1);
        g_csr[pos] = s;
    }
}

// ---------------- pull + fused z epilogue -----------------------------------
// One warp/node; lane = 8*q + c. Each lane loads 8 halves of neighbor t+q:
// one warp-wide load covers 4 neighbors. fp32 accumulation. After the
// cross-quad reduction, q==0 lanes read their own y16 row and write
// z = fp16(relu((1+eps)*y + agg + b1)) — gemm2 then just copies z16.
__global__ void __launch_bounds__(256) k_pull64(const float* __restrict__ eps,
                                                int layer,
                                                const float* __restrict__ B1) {
    int node = (blockIdx.x * 256 + threadIdx.x) >> 5;
    int lane = threadIdx.x & 31;
    if (node >= NN) return;
    const int q = lane >> 3;      // neighbor slot 0..3
    const int c = lane & 7;       // 8-half chunk 0..7
    int beg = g_rowptr[node], end = g_rowptr[node + 1];

    float2 a0 = make_float2(0.f, 0.f), a1 = a0, a2 = a0, a3 = a0;
    for (int j = beg; j < end; j += 32) {
        int n = min(32, end - j);
        int idx = (lane < n) ? g_csr[j + lane] : 0;
        int t = 0;
        for (; t + 16 <= n; t += 16) {
            int u0 = __shfl_sync(0xffffffffu, idx, t + 0 + q);
            int u1 = __shfl_sync(0xffffffffu, idx, t + 4 + q);
            int u2 = __shfl_sync(0xffffffffu, idx, t + 8 + q);
            int u3 = __shfl_sync(0xffffffffu, idx, t + 12 + q);
            uint4 r0 = *(const uint4*)&g_y16[(long)u0 * HH + c * 8];
            uint4 r1 = *(const uint4*)&g_y16[(long)u1 * HH + c * 8];
            uint4 r2 = *(const uint4*)&g_y16[(long)u2 * HH + c * 8];
            uint4 r3 = *(const uint4*)&g_y16[(long)u3 * HH + c * 8];
            acc8(r0, a0, a1, a2, a3);
            acc8(r1, a0, a1, a2, a3);
            acc8(r2, a0, a1, a2, a3);
            acc8(r3, a0, a1, a2, a3);
        }
        for (; t < n; t += 4) {
            int tt = t + q;
            int sel = (tt < n) ? tt : t;
            int u = __shfl_sync(0xffffffffu, idx, sel);
            uint4 r = *(const uint4*)&g_y16[(long)u * HH + c * 8];
            if (tt < n) acc8(r, a0, a1, a2, a3);
        }
    }
#pragma unroll
    for (int o = 8; o <= 16; o <<= 1) {
        a0.x += __shfl_xor_sync(0xffffffffu, a0.x, o);
        a0.y += __shfl_xor_sync(0xffffffffu, a0.y, o);
        a1.x += __shfl_xor_sync(0xffffffffu, a1.x, o);
        a1.y += __shfl_xor_sync(0xffffffffu, a1.y, o);
        a2.x += __shfl_xor_sync(0xffffffffu, a2.x, o);
        a2.y += __shfl_xor_sync(0xffffffffu, a2.y, o);
        a3.x += __shfl_xor_sync(0xffffffffu, a3.x, o);
        a3.y += __shfl_xor_sync(0xffffffffu, a3.y, o);
    }
    if (q == 0) {
        const float epsv = 1.0f + eps[layer];
        uint4 yr = *(const uint4*)&g_y16[(long)node * HH + c * 8];
        float2 y0 = __half22float2(*(const __half2*)&yr.x);
        float2 y1 = __half22float2(*(const __half2*)&yr.y);
        float2 y2 = __half22float2(*(const __half2*)&yr.z);
        float2 y3 = __half22float2(*(const __half2*)&yr.w);
        float4 ba = *(const float4*)&B1[c * 8];
        float4 bb = *(const float4*)&B1[c * 8 + 4];
        float z0 = fmaxf(epsv * y0.x + a0.x + ba.x, 0.f);
        float z1 = fmaxf(epsv * y0.y + a0.y + ba.y, 0.f);
        float z2 = fmaxf(epsv * y1.x + a1.x + ba.z, 0.f);
        float z3 = fmaxf(epsv * y1.y + a1.y + ba.w, 0.f);
        float z4 = fmaxf(epsv * y2.x + a2.x + bb.x, 0.f);
        float z5 = fmaxf(epsv * y2.y + a2.y + bb.y, 0.f);
        float z6 = fmaxf(epsv * y3.x + a3.x + bb.z, 0.f);
        float z7 = fmaxf(epsv * y3.y + a3.y + bb.w, 0.f);
        __half2 h0 = __floats2half2_rn(z0, z1);
        __half2 h1 = __floats2half2_rn(z2, z3);
        __half2 h2 = __floats2half2_rn(z4, z5);
        __half2 h3 = __floats2half2_rn(z6, z7);
        uint4 o;
        o.x = *(unsigned*)&h0; o.y = *(unsigned*)&h1;
        o.z = *(unsigned*)&h2; o.w = *(unsigned*)&h3;
        *(uint4*)&g_z16[(long)node * HH + c * 8] = o;
    }
}

// ---------------- GEMM2: h = relu(z16@W2+b2); opt y_next = h @ W1_next ------
__global__ void __launch_bounds__(256) k_gemm2(int layer,
                                               const float* __restrict__ B2,
                                               int out_off, int has_next) {
    __shared__ __align__(16) __half sA[64][72];
    __shared__ __align__(16) __half sB[64][72];
    __shared__ __align__(16) float  sC[64][72];

    const int tid = threadIdx.x;
    const int wid = tid >> 5;
    const int tile = blockIdx.x * 64;

    // Stage z16 and W2 (pure fp16 copies)
#pragma unroll
    for (int s = 0; s < 2; s++) {
        int slot = tid + s * 256;               // 0..511 uint4
        int row = slot >> 3;
        int c8  = slot & 7;
        *(uint4*)&sA[row][c8 * 8] = *(const uint4*)&g_z16[(long)(tile + row) * HH + c8 * 8];
        *(uint4*)&sB[row][c8 * 8] = *(const uint4*)&g_w2h[layer][row * 64 + c8 * 8];
    }
    __syncthreads();

    const int row0 = (wid >> 1) * 16;
    const int col0 = (wid & 1) * 32;

    wmma::fragment<wmma::accumulator, 16, 16, 16, float> c0, c1;
    wmma::fill_fragment(c0, 0.f);
    wmma::fill_fragment(c1, 0.f);
#pragma unroll
    for (int k = 0; k < 4; k++) {
        wmma::fragment<wmma::matrix_a, 16, 16, 16, __half, wmma::row_major> a;
        wmma::fragment<wmma::matrix_b, 16, 16, 16, __half, wmma::row_major> b0, b1;
        wmma::load_matrix_sync(a, &sA[row0][k * 16], 72);
        wmma::load_matrix_sync(b0, &sB[k * 16][col0], 72);
        wmma::load_matrix_sync(b1, &sB[k * 16][col0 + 16], 72);
        wmma::mma_sync(c0, a, b0, c0);
        wmma::mma_sync(c1, a, b1, c1);
    }
    wmma::store_matrix_sync(&sC[row0][col0], c0, 72, wmma::mem_row_major);
    wmma::store_matrix_sync(&sC[row0][col0 + 16], c1, 72, wmma::mem_row_major);
    __syncthreads();

    // Epilogue: h = relu(sC + b2) -> g_hs16 (+ sA/sB for phase 2)
#pragma unroll
    for (int s = 0; s < 4; s++) {
        int slot = tid + s * 256;
        int row = slot >> 4;
        int c4  = slot & 15;
        float4 v = *(const float4*)&sC[row][c4 * 4];
        float4 bv = *(const float4*)&B2[c4 * 4];
        v.x = fmaxf(v.x + bv.x, 0.f);
        v.y = fmaxf(v.y + bv.y, 0.f);
        v.z = fmaxf(v.z + bv.z, 0.f);
        v.w = fmaxf(v.w + bv.w, 0.f);
        __half2 h01 = __floats2half2_rn(v.x, v.y);
        __half2 h23 = __floats2half2_rn(v.z, v.w);
        uint2 u;
        u.x = *(unsigned*)&h01;
        u.y = *(unsigned*)&h23;
        *(uint2*)&g_hs16[(long)(tile + row) * HS + out_off + c4 * 4] = u;
        *(uint2*)&sA[row][c4 * 4] = u;
    }
    if (!has_next) return;
#pragma unroll
    for (int s = 0; s < 2; s++) {
        int slot = tid + s * 256;
        int row = slot >> 3;
        int c8  = slot & 7;
        *(uint4*)&sB[row][c8 * 8] = *(const uint4*)&g_w1hn[layer][row * 64 + c8 * 8];
    }
    __syncthreads();

    // Phase 2: y_next = h @ W1_next
    wmma::fill_fragment(c0, 0.f);
    wmma::fill_fragment(c1, 0.f);
#pragma unroll
    for (int k = 0; k < 4; k++) {
        wmma::fragment<wmma::matrix_a, 16, 16, 16, __half, wmma::row_major> a;
        wmma::fragment<wmma::matrix_b, 16, 16, 16, __half, wmma::row_major> b0, b1;
        wmma::load_matrix_sync(a, &sA[row0][k * 16], 72);
        wmma::load_matrix_sync(b0, &sB[k * 16][col0], 72);
        wmma::load_matrix_sync(b1, &sB[k * 16][col0 + 16], 72);
        wmma::mma_sync(c0, a, b0, c0);
        wmma::mma_sync(c1, a, b1, c1);
    }
    __syncthreads();     // all epilogue reads of sC are done
    wmma::store_matrix_sync(&sC[row0][col0], c0, 72, wmma::mem_row_major);
    wmma::store_matrix_sync(&sC[row0][col0 + 16], c1, 72, wmma::mem_row_major);
    __syncthreads();

#pragma unroll
    for (int s = 0; s < 4; s++) {
        int slot = tid + s * 256;
        int row = slot >> 4;
        int c4  = slot & 15;
        float4 v = *(const float4*)&sC[row][c4 * 4];
        f4_to_h4(v, &g_y16[(long)(tile + row) * HH + c4 * 4]);
    }
}

// ---------------- readout (binary-search offsets fused in) ------------------
__global__ void __launch_bounds__(192) k_readout(const void* __restrict__ batch,
                                                 const float* __restrict__ fc1w,
                                                 const float* __restrict__ fc1b,
                                                 const float* __restrict__ fc2w,
                                                 const float* __restrict__ fc2b,
                                                 float* __restrict__ out) {
    __shared__ float gv[GF];
    __shared__ float q[HH];
    __shared__ int bound[2];

    int g = blockIdx.x;
    int f = threadIdx.x;

    // threads 0/1 compute segment bounds via binary search (batch is sorted)
    if (f < 2) {
        int target = g + f;
        int lo = 0, hi = NN;
        if (target == NG) lo = NN;
        else {
            while (lo < hi) {
                int mid = (lo + hi) >> 1;
                if ((int)ld_idx(batch, mid) < target) lo = mid + 1; else hi = mid;
            }
        }
        bound[f] = lo;
    }
    __syncthreads();
    int n0 = bound[0], n1 = bound[1];

    float s = 0.f, m = -3.402823466e38f;
    for (int n = n0; n < n1; n++) {
        float v = __half2float(g_hs16[(long)n * HS + f]);
        s += v;
        m = fmaxf(m, v);
    }
    int cnt = n1 - n0;
    gv[f]       = s / fmaxf((float)cnt, 1.f);
    gv[192 + f] = m;
    gv[384 + f] = s;
    __syncthreads();

    if (f < HH) {
        float a = fc1b[f];
#pragma unroll 4
        for (int k = 0; k < GF; k++) a += gv[k] * fc1w[k * 64 + f];
        q[f] = fmaxf(a, 0.f);
    }
    __syncthreads();

    if (f < 2) {
        float a = fc2b[f];
#pragma unroll
        for (int k = 0; k < HH; k++) a += q[k] * fc2w[k * 2 + f];
        out[g * 2 + f] = 1.f / (1.f + expf(-a));
    }
}

// ---------------- launch ----------------------------------------------------
extern "C" void kernel_launch(void* const* d_in, const int* in_sizes, int n_in,
                              void* d_out, int out_size) {
    const float* x     = (const float*)d_in[0];
    const void*  edge  = d_in[1];
    const void*  batch = d_in[2];
    const float* w1[3] = {(const float*)d_in[3],  (const float*)d_in[7],  (const float*)d_in[11]};
    const float* b1[3] = {(const float*)d_in[4],  (const float*)d_in[8],  (const float*)d_in[12]};
    const float* w2[3] = {(const float*)d_in[5],  (const float*)d_in[9],  (const float*)d_in[13]};
    const float* b2[3] = {(const float*)d_in[6],  (const float*)d_in[10], (const float*)d_in[14]};
    const float* eps   = (const float*)d_in[15];
    const float* fc1w  = (const float*)d_in[16];
    const float* fc1b  = (const float*)d_in[17];
    const float* fc2w  = (const float*)d_in[18];
    const float* fc2b  = (const float*)d_in[19];

    // probe + zero degrees + ticket/done + weight conversion
    k_prep<<<(NN + 255) / 256, 256>>>(edge, w1[0], w1[1], w1[2], w2[0], w2[1], w2[2]);

    // gemm1 (y0 = x @ W1_0) co-scheduled with degree histogram
    k_par1<<<GEMM1_GRID + DEG_GRID, 256>>>(x, edge);

    // CSR scan (single kernel, resident-grid phases) + fill
    k_csr<<<NSB, 256>>>();
    k_fill<<<DEG_GRID, 256>>>(edge);

    const int pull_grid = (NN + 7) / 8;
    for (int L = 0; L < 3; L++) {
        k_pull64<<<pull_grid, 256>>>(eps, L, b1[L]);
        const int has_next = (L < 2) ? 1 : 0;
        k_gemm2<<<GEMM1_GRID, 256>>>(L, b2[L], L * 64, has_next);
    }

    k_readout<<<NG, 192>>>(batch, fc1w, fc1b, fc2w, fc2b, (float*)d_out);
}